// round 6
// baseline (speedup 1.0000x reference)
#include <cuda_runtime.h>
#include <math_constants.h>

#define BB 2
#define LL 2048
#define HH 1024
#define NHEAD 16
#define HD 64
#define SOFTMAX_SCALE (1.0f / 32.0f)
#define FMIN (-3.402823466e38f)

// Scratch (device globals: allocation-free rule)
__device__ float g_Q[BB * LL * HH];
__device__ float g_K[BB * LL * HH];
__device__ float g_V[BB * LL * HH];
__device__ float g_C[BB * LL * HH];
__device__ float g_X[BB * LL * HH];
__device__ float g_Wq[HH * HH];
__device__ float g_Wk[HH * HH];
__device__ float g_Wv[HH * HH];
__device__ float g_Wo[HH * HH];

// ---------------------------------------------------------------------------
// helpers
// ---------------------------------------------------------------------------
__device__ __forceinline__ unsigned f2tf(float x) {
    unsigned r;
    asm("cvt.rna.tf32.f32 %0, %1;" : "=r"(r) : "f"(x));
    return r;
}
__device__ __forceinline__ float frnd(float x) { return __uint_as_float(f2tf(x)); }

__device__ __forceinline__ void mma_tf32(float* d, const unsigned* a, const unsigned* b) {
    asm volatile(
        "mma.sync.aligned.m16n8k8.row.col.f32.tf32.tf32.f32 "
        "{%0,%1,%2,%3}, {%4,%5,%6,%7}, {%8,%9}, {%0,%1,%2,%3};"
        : "+f"(d[0]), "+f"(d[1]), "+f"(d[2]), "+f"(d[3])
        : "r"(a[0]), "r"(a[1]), "r"(a[2]), "r"(a[3]), "r"(b[0]), "r"(b[1]));
}

__device__ __forceinline__ void cp16(void* dst_smem, const void* src) {
    unsigned d = (unsigned)__cvta_generic_to_shared(dst_smem);
    asm volatile("cp.async.cg.shared.global [%0], [%1], 16;" :: "r"(d), "l"(src));
}
__device__ __forceinline__ void cp_commit() { asm volatile("cp.async.commit_group;"); }
__device__ __forceinline__ void cp_wait0() { asm volatile("cp.async.wait_group 0;"); }
__device__ __forceinline__ void cp_wait1() { asm volatile("cp.async.wait_group 1;"); }
__device__ __forceinline__ void cp_wait2() { asm volatile("cp.async.wait_group 2;"); }

// P (softmax C-fragment) -> tf32 A-fragment via shuffles
__device__ __forceinline__ void p_to_afrag(const float* sv, unsigned* af,
                                           int lane, int j) {
    unsigned pc0 = f2tf(sv[0]), pc1 = f2tf(sv[1]);
    unsigned pc2 = f2tf(sv[2]), pc3 = f2tf(sv[3]);
    int src = (lane & ~3) | (j >> 1);
    int src2 = src + 2;
    unsigned x0 = __shfl_sync(0xffffffffu, pc0, src);
    unsigned x1 = __shfl_sync(0xffffffffu, pc1, src);
    unsigned y0 = __shfl_sync(0xffffffffu, pc2, src);
    unsigned y1 = __shfl_sync(0xffffffffu, pc3, src);
    unsigned x0b = __shfl_sync(0xffffffffu, pc0, src2);
    unsigned x1b = __shfl_sync(0xffffffffu, pc1, src2);
    unsigned y0b = __shfl_sync(0xffffffffu, pc2, src2);
    unsigned y1b = __shfl_sync(0xffffffffu, pc3, src2);
    af[0] = (lane & 1) ? x1 : x0;
    af[1] = (lane & 1) ? y1 : y0;
    af[2] = (lane & 1) ? x1b : x0b;
    af[3] = (lane & 1) ? y1b : y0b;
}

// ---------------------------------------------------------------------------
// Pre-round inputs to tf32 (RNA) once.
// ---------------------------------------------------------------------------
__device__ __forceinline__ float4 rnd4(float4 v) {
    return make_float4(frnd(v.x), frnd(v.y), frnd(v.z), frnd(v.w));
}

__global__ void __launch_bounds__(256)
preconv_kernel(const float* __restrict__ x, const float* __restrict__ wq,
               const float* __restrict__ wk, const float* __restrict__ wv,
               const float* __restrict__ wo) {
    int i = blockIdx.x * blockDim.x + threadIdx.x;
    int stride = gridDim.x * blockDim.x;
    const int NX = BB * LL * HH / 4;
    const int NW = HH * HH / 4;
    for (int k = i; k < NX; k += stride)
        ((float4*)g_X)[k] = rnd4(((const float4*)x)[k]);
    for (int k = i; k < NW; k += stride) {
        ((float4*)g_Wq)[k] = rnd4(((const float4*)wq)[k]);
        ((float4*)g_Wk)[k] = rnd4(((const float4*)wk)[k]);
        ((float4*)g_Wv)[k] = rnd4(((const float4*)wv)[k]);
        ((float4*)g_Wo)[k] = rnd4(((const float4*)wo)[k]);
    }
}

// ---------------------------------------------------------------------------
// tf32 GEMM: C[4096,1024] = A @ W, BM=BN=128, BK=32, 3-stage cp.async.
// (unchanged from R4 — known good)
// ---------------------------------------------------------------------------
#define GKT 32

template <bool ROUND>
__device__ __forceinline__ void gemm_body(const float* __restrict__ A,
                                          const float* __restrict__ W,
                                          float* __restrict__ C) {
    extern __shared__ float sm[];

    const int tid = threadIdx.x;
    const int lane = tid & 31;
    const int wid = tid >> 5;
    const int wm = (wid >> 2) * 64;
    const int wn = (wid & 3) * 32;
    const int m0 = blockIdx.y * 128;
    const int n0 = blockIdx.x * 128;
    const int r0 = lane >> 2;
    const int j = lane & 3;

    const float* Ap = A + m0 * 1024;
    const float* Wp = W + n0;

    auto issue = [&](int it) {
        const int k0 = it * 32;
        float* As = sm + (it % 3) * 8192;
        float* Bs = As + 4096;
#pragma unroll
        for (int t = 0; t < 4; t++) {
            int id = tid + t * 256;
            int ra = id >> 3, ca = id & 7;
            cp16(&As[ra * 32 + ((ca ^ (ra & 7)) << 2)],
                 &Ap[ra * 1024 + k0 + (ca << 2)]);
            int rb = id >> 5, cb = id & 31;
            cp16(&Bs[rb * 128 + ((cb ^ ((rb & 3) << 1)) << 2)],
                 &Wp[(k0 + rb) * 1024 + (cb << 2)]);
        }
        cp_commit();
    };

    float acc[4][4][4];
#pragma unroll
    for (int mt = 0; mt < 4; mt++)
#pragma unroll
        for (int nt = 0; nt < 4; nt++)
#pragma unroll
            for (int i = 0; i < 4; i++) acc[mt][nt][i] = 0.0f;

    issue(0);
    issue(1);

    for (int it = 0; it < GKT; it++) {
        if (it == GKT - 1) cp_wait0(); else cp_wait1();
        __syncthreads();
        if (it + 2 < GKT) issue(it + 2);

        const float* As = sm + (it % 3) * 8192;
        const float* Bs = As + 4096;

#pragma unroll
        for (int kk = 0; kk < 4; kk++) {
            const int k8 = kk << 3;
            const int pA0 = (((kk << 1) ^ r0) << 2) + j;
            const int pA1 = ((((kk << 1) | 1) ^ r0) << 2) + j;
            unsigned af[4][4], bf[4][2];
#pragma unroll
            for (int mt = 0; mt < 4; mt++) {
                const float* base = As + (wm + mt * 16 + r0) * 32;
                af[mt][0] = __float_as_uint(base[pA0]);
                af[mt][1] = __float_as_uint(base[8 * 32 + pA0]);
                af[mt][2] = __float_as_uint(base[pA1]);
                af[mt][3] = __float_as_uint(base[8 * 32 + pA1]);
            }
#pragma unroll
            for (int nt = 0; nt < 4; nt++) {
                const int bn = wn + nt * 8;
                const int phys = (((((bn + r0) >> 2) ^ (j << 1)) << 2) | (r0 & 3));
                bf[nt][0] = __float_as_uint(Bs[(k8 + j) * 128 + phys]);
                bf[nt][1] = __float_as_uint(Bs[(k8 + 4 + j) * 128 + phys]);
            }
#pragma unroll
            for (int mt = 0; mt < 4; mt++)
#pragma unroll
                for (int nt = 0; nt < 4; nt++)
                    mma_tf32(acc[mt][nt], af[mt], bf[nt]);
        }
    }

#pragma unroll
    for (int mt = 0; mt < 4; mt++) {
        int rr = m0 + wm + mt * 16 + r0;
#pragma unroll
        for (int nt = 0; nt < 4; nt++) {
            int cc = n0 + wn + nt * 8 + (j << 1);
            if (ROUND) {
                *(float2*)&C[rr * 1024 + cc] =
                    make_float2(frnd(acc[mt][nt][0]), frnd(acc[mt][nt][1]));
                *(float2*)&C[(rr + 8) * 1024 + cc] =
                    make_float2(frnd(acc[mt][nt][2]), frnd(acc[mt][nt][3]));
            } else {
                *(float2*)&C[rr * 1024 + cc] =
                    make_float2(acc[mt][nt][0], acc[mt][nt][1]);
                *(float2*)&C[(rr + 8) * 1024 + cc] =
                    make_float2(acc[mt][nt][2], acc[mt][nt][3]);
            }
        }
    }
}

__global__ void __launch_bounds__(256, 2)
gemm_qkv() {
    const float* W = (blockIdx.z == 0) ? g_Wq : (blockIdx.z == 1) ? g_Wk : g_Wv;
    float* C = (blockIdx.z == 0) ? g_Q : (blockIdx.z == 1) ? g_K : g_V;
    gemm_body<true>(g_X, W, C);
}

__global__ void __launch_bounds__(256, 2)
gemm_out(float* __restrict__ out) {
    gemm_body<false>(g_C, g_Wo, out);
}

// ---------------------------------------------------------------------------
// Flash attention, tf32 mma. Block = 128 q rows, 128 threads (4 warps).
// Warp w owns rows w*32..w*32+31 (2 m-tiles of 16): each K/V fragment load
// feeds 2 MMAs (LDS/MMA halved vs 16-row warps).
// Dyn smem: K[2][4096] | V[2][4096] | am[2][64]  (66048 B)
// ---------------------------------------------------------------------------
__global__ void __launch_bounds__(128)
attn_kernel(const float* __restrict__ am) {
    extern __shared__ float sm[];

    const int tid = threadIdx.x;
    const int lane = tid & 31;
    const int w = tid >> 5;
    const int qt = (int)gridDim.x - 1 - (int)blockIdx.x;  // longest blocks first
    const int q0 = qt * 128;
    const int h = blockIdx.y;
    const int b = blockIdx.z;
    const int bL = b * LL;
    const int r0 = lane >> 2;
    const int j = lane & 3;

    auto issue = [&](int ti) {
        const int k0 = ti * 64;
        const int s = ti & 1;
        float* Ks = sm + s * 4096;
        float* Vs = sm + 8192 + s * 4096;
        float* ams = sm + 16384 + s * 64;
#pragma unroll
        for (int t = 0; t < 8; t++) {
            int id = tid + t * 128;
            int r = id >> 4, c = id & 15;
            const float* gk = &g_K[(bL + k0 + r) * HH + h * HD + (c << 2)];
            const float* gv = &g_V[(bL + k0 + r) * HH + h * HD + (c << 2)];
            cp16(&Ks[r * 64 + ((c ^ (r & 7)) << 2)], gk);
            cp16(&Vs[r * 64 + ((c ^ ((r & 3) << 1)) << 2)], gv);
        }
        if (tid < 16) cp16(&ams[tid << 2], &am[bL + k0 + (tid << 2)]);
        cp_commit();
    };

    // Q fragments for both m-tiles (pre-rounded -> raw bits are valid tf32)
    unsigned qa[2][8][4];
    float amq[2][2];
    int qi[2][2];
#pragma unroll
    for (int mt = 0; mt < 2; mt++) {
        const float* Qp = g_Q + (bL + q0 + w * 32 + mt * 16) * HH + h * HD;
#pragma unroll
        for (int ks = 0; ks < 8; ks++) {
            qa[mt][ks][0] = __float_as_uint(Qp[r0 * HH + ks * 8 + j]);
            qa[mt][ks][1] = __float_as_uint(Qp[(r0 + 8) * HH + ks * 8 + j]);
            qa[mt][ks][2] = __float_as_uint(Qp[r0 * HH + ks * 8 + j + 4]);
            qa[mt][ks][3] = __float_as_uint(Qp[(r0 + 8) * HH + ks * 8 + j + 4]);
        }
        qi[mt][0] = q0 + w * 32 + mt * 16 + r0;
        qi[mt][1] = qi[mt][0] + 8;
        amq[mt][0] = am[bL + qi[mt][0]];
        amq[mt][1] = am[bL + qi[mt][1]];
    }

    float o[2][8][4] = {};
    float mr[2][2] = {{-CUDART_INF_F, -CUDART_INF_F}, {-CUDART_INF_F, -CUDART_INF_F}};
    float lsum[2][2] = {};

    const int ntiles = q0 / 64 + 2;
    issue(0);

    for (int ti = 0; ti < ntiles; ti++) {
        const int k0 = ti * 64;
        cp_wait0();
        __syncthreads();
        if (ti + 1 < ntiles) issue(ti + 1);

        // Warp-level skip: all 32 of this warp's rows strictly below k0 ->
        // tile contributes exactly 0 (corr=1, rs=0). Exact.
        if (k0 > q0 + w * 32 + 31) continue;

        const float* Ks = sm + (ti & 1) * 4096;
        const float* Vs = sm + 8192 + (ti & 1) * 4096;
        const float* ams = sm + 16384 + (ti & 1) * 64;

        // S = Q K^T for both m-tiles, sharing K fragments
        float s[2][8][4] = {};
#pragma unroll
        for (int ks = 0; ks < 8; ks++) {
            const int pK0 = (((ks << 1) ^ r0) << 2) + j;
            const int pK1 = ((((ks << 1) | 1) ^ r0) << 2) + j;
#pragma unroll
            for (int nt = 0; nt < 8; nt++) {
                unsigned bf[2];
                bf[0] = __float_as_uint(Ks[(nt * 8 + r0) * 64 + pK0]);
                bf[1] = __float_as_uint(Ks[(nt * 8 + r0) * 64 + pK1]);
                mma_tf32(s[0][nt], qa[0][ks], bf);
                mma_tf32(s[1][nt], qa[1][ks], bf);
            }
        }

        // Mask + online softmax per m-tile
#pragma unroll
        for (int mt = 0; mt < 2; mt++) {
            float nm0 = mr[mt][0], nm1 = mr[mt][1];
#pragma unroll
            for (int nt = 0; nt < 8; nt++) {
                int kc = k0 + nt * 8 + (j << 1);
                float2 ak = *(const float2*)&ams[nt * 8 + (j << 1)];
                float mk00 = fmaxf((kc > qi[mt][0]) ? 1.f : 0.f, 1.f - amq[mt][0] * ak.x);
                float mk01 = fmaxf((kc + 1 > qi[mt][0]) ? 1.f : 0.f, 1.f - amq[mt][0] * ak.y);
                float mk10 = fmaxf((kc > qi[mt][1]) ? 1.f : 0.f, 1.f - amq[mt][1] * ak.x);
                float mk11 = fmaxf((kc + 1 > qi[mt][1]) ? 1.f : 0.f, 1.f - amq[mt][1] * ak.y);
                s[mt][nt][0] = (s[mt][nt][0] + FMIN * mk00) * SOFTMAX_SCALE;
                s[mt][nt][1] = (s[mt][nt][1] + FMIN * mk01) * SOFTMAX_SCALE;
                s[mt][nt][2] = (s[mt][nt][2] + FMIN * mk10) * SOFTMAX_SCALE;
                s[mt][nt][3] = (s[mt][nt][3] + FMIN * mk11) * SOFTMAX_SCALE;
                nm0 = fmaxf(nm0, fmaxf(s[mt][nt][0], s[mt][nt][1]));
                nm1 = fmaxf(nm1, fmaxf(s[mt][nt][2], s[mt][nt][3]));
            }
            nm0 = fmaxf(nm0, __shfl_xor_sync(0xffffffffu, nm0, 1));
            nm0 = fmaxf(nm0, __shfl_xor_sync(0xffffffffu, nm0, 2));
            nm1 = fmaxf(nm1, __shfl_xor_sync(0xffffffffu, nm1, 1));
            nm1 = fmaxf(nm1, __shfl_xor_sync(0xffffffffu, nm1, 2));

            float corr0 = __expf(mr[mt][0] - nm0);
            float corr1 = __expf(mr[mt][1] - nm1);
            mr[mt][0] = nm0; mr[mt][1] = nm1;

            float rs0 = 0.0f, rs1 = 0.0f;
#pragma unroll
            for (int nt = 0; nt < 8; nt++) {
                s[mt][nt][0] = __expf(s[mt][nt][0] - nm0);
                s[mt][nt][1] = __expf(s[mt][nt][1] - nm0);
                s[mt][nt][2] = __expf(s[mt][nt][2] - nm1);
                s[mt][nt][3] = __expf(s[mt][nt][3] - nm1);
                rs0 += s[mt][nt][0] + s[mt][nt][1];
                rs1 += s[mt][nt][2] + s[mt][nt][3];
            }
            rs0 += __shfl_xor_sync(0xffffffffu, rs0, 1);
            rs0 += __shfl_xor_sync(0xffffffffu, rs0, 2);
            rs1 += __shfl_xor_sync(0xffffffffu, rs1, 1);
            rs1 += __shfl_xor_sync(0xffffffffu, rs1, 2);
            lsum[mt][0] = lsum[mt][0] * corr0 + rs0;
            lsum[mt][1] = lsum[mt][1] * corr1 + rs1;
#pragma unroll
            for (int dt = 0; dt < 8; dt++) {
                o[mt][dt][0] *= corr0; o[mt][dt][1] *= corr0;
                o[mt][dt][2] *= corr1; o[mt][dt][3] *= corr1;
            }
        }

        // O += P @ V, sharing V fragments across both m-tiles
#pragma unroll
        for (int nt = 0; nt < 8; nt++) {
            unsigned af0[4], af1[4];
            p_to_afrag(s[0][nt], af0, lane, j);
            p_to_afrag(s[1][nt], af1, lane, j);
#pragma unroll
            for (int dt = 0; dt < 8; dt++) {
                const int pv = ((((dt << 1) | (r0 >> 2)) ^ (j << 1)) << 2) | (r0 & 3);
                unsigned bf[2];
                bf[0] = __float_as_uint(Vs[(nt * 8 + j) * 64 + pv]);
                bf[1] = __float_as_uint(Vs[(nt * 8 + 4 + j) * 64 + pv]);
                mma_tf32(o[0][dt], af0, bf);
                mma_tf32(o[1][dt], af1, bf);
            }
        }
    }

    // Normalize, round (next GEMM consumes as tf32), write ctx
#pragma unroll
    for (int mt = 0; mt < 2; mt++) {
        float inv0 = 1.0f / lsum[mt][0], inv1 = 1.0f / lsum[mt][1];
        float* Cp = g_C + (bL + q0 + w * 32 + mt * 16) * HH + h * HD;
#pragma unroll
        for (int dt = 0; dt < 8; dt++) {
            int c = dt * 8 + (j << 1);
            *(float2*)&Cp[r0 * HH + c] =
                make_float2(frnd(o[mt][dt][0] * inv0), frnd(o[mt][dt][1] * inv0));
            *(float2*)&Cp[(r0 + 8) * HH + c] =
                make_float2(frnd(o[mt][dt][2] * inv1), frnd(o[mt][dt][3] * inv1));
        }
    }
}

// ---------------------------------------------------------------------------
extern "C" void kernel_launch(void* const* d_in, const int* in_sizes, int n_in,
                              void* d_out, int out_size) {
    const float* input = (const float*)d_in[0];
    const float* amask = (const float*)d_in[1];
    const float* wq = (const float*)d_in[2];
    const float* wk = (const float*)d_in[3];
    const float* wv = (const float*)d_in[4];
    const float* wo = (const float*)d_in[5];
    float* out = (float*)d_out;

    static bool attr_done = false;
    if (!attr_done) {
        cudaFuncSetAttribute(gemm_qkv, cudaFuncAttributeMaxDynamicSharedMemorySize, 98304);
        cudaFuncSetAttribute(gemm_out, cudaFuncAttributeMaxDynamicSharedMemorySize, 98304);
        cudaFuncSetAttribute(attn_kernel, cudaFuncAttributeMaxDynamicSharedMemorySize, 66048);
        attr_done = true;
    }

    preconv_kernel<<<2048, 256>>>(input, wq, wk, wv, wo);
    gemm_qkv<<<dim3(8, 32, 3), 256, 98304>>>();
    attn_kernel<<<dim3(LL / 128, NHEAD, BB), 128, 66048>>>(amask);
    gemm_out<<<dim3(8, 32), 256, 98304>>>(out);
}

// round 10
// speedup vs baseline: 1.0626x; 1.0626x over previous
#include <cuda_runtime.h>
#include <math_constants.h>

#define BB 2
#define LL 2048
#define HH 1024
#define NHEAD 16
#define HD 64
#define SOFTMAX_SCALE (1.0f / 32.0f)
#define FMIN (-3.402823466e38f)

// Scratch (device globals: allocation-free rule)
__device__ float g_Q[BB * LL * HH];
__device__ float g_K[BB * LL * HH];
__device__ float g_V[BB * LL * HH];
__device__ float g_C[BB * LL * HH];
__device__ float g_X[BB * LL * HH];
__device__ float g_Wq[HH * HH];
__device__ float g_Wk[HH * HH];
__device__ float g_Wv[HH * HH];
__device__ float g_Wo[HH * HH];

// ---------------------------------------------------------------------------
// helpers
// ---------------------------------------------------------------------------
__device__ __forceinline__ unsigned f2tf(float x) {
    unsigned r;
    asm("cvt.rna.tf32.f32 %0, %1;" : "=r"(r) : "f"(x));
    return r;
}
__device__ __forceinline__ float frnd(float x) { return __uint_as_float(f2tf(x)); }

__device__ __forceinline__ void mma_tf32(float* d, const unsigned* a, const unsigned* b) {
    asm volatile(
        "mma.sync.aligned.m16n8k8.row.col.f32.tf32.tf32.f32 "
        "{%0,%1,%2,%3}, {%4,%5,%6,%7}, {%8,%9}, {%0,%1,%2,%3};"
        : "+f"(d[0]), "+f"(d[1]), "+f"(d[2]), "+f"(d[3])
        : "r"(a[0]), "r"(a[1]), "r"(a[2]), "r"(a[3]), "r"(b[0]), "r"(b[1]));
}

__device__ __forceinline__ void cp16(void* dst_smem, const void* src) {
    unsigned d = (unsigned)__cvta_generic_to_shared(dst_smem);
    asm volatile("cp.async.cg.shared.global [%0], [%1], 16;" :: "r"(d), "l"(src));
}
__device__ __forceinline__ void cp_commit() { asm volatile("cp.async.commit_group;"); }
__device__ __forceinline__ void cp_wait0() { asm volatile("cp.async.wait_group 0;"); }
__device__ __forceinline__ void cp_wait1() { asm volatile("cp.async.wait_group 1;"); }

// ---------------------------------------------------------------------------
// Pre-round inputs to tf32 (RNA) once.
// ---------------------------------------------------------------------------
__device__ __forceinline__ float4 rnd4(float4 v) {
    return make_float4(frnd(v.x), frnd(v.y), frnd(v.z), frnd(v.w));
}

__global__ void __launch_bounds__(256)
preconv_kernel(const float* __restrict__ x, const float* __restrict__ wq,
               const float* __restrict__ wk, const float* __restrict__ wv,
               const float* __restrict__ wo) {
    int i = blockIdx.x * blockDim.x + threadIdx.x;
    int stride = gridDim.x * blockDim.x;
    const int NX = BB * LL * HH / 4;
    const int NW = HH * HH / 4;
    for (int k = i; k < NX; k += stride)
        ((float4*)g_X)[k] = rnd4(((const float4*)x)[k]);
    for (int k = i; k < NW; k += stride) {
        ((float4*)g_Wq)[k] = rnd4(((const float4*)wq)[k]);
        ((float4*)g_Wk)[k] = rnd4(((const float4*)wk)[k]);
        ((float4*)g_Wv)[k] = rnd4(((const float4*)wv)[k]);
        ((float4*)g_Wo)[k] = rnd4(((const float4*)wo)[k]);
    }
}

// ---------------------------------------------------------------------------
// tf32 GEMM: C[4096,1024] = A @ W, BM=BN=128, BK=32, 3-stage cp.async.
// (unchanged from R4 — known good)
// ---------------------------------------------------------------------------
#define GKT 32

template <bool ROUND>
__device__ __forceinline__ void gemm_body(const float* __restrict__ A,
                                          const float* __restrict__ W,
                                          float* __restrict__ C) {
    extern __shared__ float sm[];

    const int tid = threadIdx.x;
    const int lane = tid & 31;
    const int wid = tid >> 5;
    const int wm = (wid >> 2) * 64;
    const int wn = (wid & 3) * 32;
    const int m0 = blockIdx.y * 128;
    const int n0 = blockIdx.x * 128;
    const int r0 = lane >> 2;
    const int j = lane & 3;

    const float* Ap = A + m0 * 1024;
    const float* Wp = W + n0;

    auto issue = [&](int it) {
        const int k0 = it * 32;
        float* As = sm + (it % 3) * 8192;
        float* Bs = As + 4096;
#pragma unroll
        for (int t = 0; t < 4; t++) {
            int id = tid + t * 256;
            int ra = id >> 3, ca = id & 7;
            cp16(&As[ra * 32 + ((ca ^ (ra & 7)) << 2)],
                 &Ap[ra * 1024 + k0 + (ca << 2)]);
            int rb = id >> 5, cb = id & 31;
            cp16(&Bs[rb * 128 + ((cb ^ ((rb & 3) << 1)) << 2)],
                 &Wp[(k0 + rb) * 1024 + (cb << 2)]);
        }
        cp_commit();
    };

    float acc[4][4][4];
#pragma unroll
    for (int mt = 0; mt < 4; mt++)
#pragma unroll
        for (int nt = 0; nt < 4; nt++)
#pragma unroll
            for (int i = 0; i < 4; i++) acc[mt][nt][i] = 0.0f;

    issue(0);
    issue(1);

    for (int it = 0; it < GKT; it++) {
        if (it == GKT - 1) cp_wait0(); else cp_wait1();
        __syncthreads();
        if (it + 2 < GKT) issue(it + 2);

        const float* As = sm + (it % 3) * 8192;
        const float* Bs = As + 4096;

#pragma unroll
        for (int kk = 0; kk < 4; kk++) {
            const int k8 = kk << 3;
            const int pA0 = (((kk << 1) ^ r0) << 2) + j;
            const int pA1 = ((((kk << 1) | 1) ^ r0) << 2) + j;
            unsigned af[4][4], bf[4][2];
#pragma unroll
            for (int mt = 0; mt < 4; mt++) {
                const float* base = As + (wm + mt * 16 + r0) * 32;
                af[mt][0] = __float_as_uint(base[pA0]);
                af[mt][1] = __float_as_uint(base[8 * 32 + pA0]);
                af[mt][2] = __float_as_uint(base[pA1]);
                af[mt][3] = __float_as_uint(base[8 * 32 + pA1]);
            }
#pragma unroll
            for (int nt = 0; nt < 4; nt++) {
                const int bn = wn + nt * 8;
                const int phys = (((((bn + r0) >> 2) ^ (j << 1)) << 2) | (r0 & 3));
                bf[nt][0] = __float_as_uint(Bs[(k8 + j) * 128 + phys]);
                bf[nt][1] = __float_as_uint(Bs[(k8 + 4 + j) * 128 + phys]);
            }
#pragma unroll
            for (int mt = 0; mt < 4; mt++)
#pragma unroll
                for (int nt = 0; nt < 4; nt++)
                    mma_tf32(acc[mt][nt], af[mt], bf[nt]);
        }
    }

#pragma unroll
    for (int mt = 0; mt < 4; mt++) {
        int rr = m0 + wm + mt * 16 + r0;
#pragma unroll
        for (int nt = 0; nt < 4; nt++) {
            int cc = n0 + wn + nt * 8 + (j << 1);
            if (ROUND) {
                *(float2*)&C[rr * 1024 + cc] =
                    make_float2(frnd(acc[mt][nt][0]), frnd(acc[mt][nt][1]));
                *(float2*)&C[(rr + 8) * 1024 + cc] =
                    make_float2(frnd(acc[mt][nt][2]), frnd(acc[mt][nt][3]));
            } else {
                *(float2*)&C[rr * 1024 + cc] =
                    make_float2(acc[mt][nt][0], acc[mt][nt][1]);
                *(float2*)&C[(rr + 8) * 1024 + cc] =
                    make_float2(acc[mt][nt][2], acc[mt][nt][3]);
            }
        }
    }
}

__global__ void __launch_bounds__(256, 2)
gemm_qkv() {
    const float* W = (blockIdx.z == 0) ? g_Wq : (blockIdx.z == 1) ? g_Wk : g_Wv;
    float* C = (blockIdx.z == 0) ? g_Q : (blockIdx.z == 1) ? g_K : g_V;
    gemm_body<true>(g_X, W, C);
}

__global__ void __launch_bounds__(256, 2)
gemm_out(float* __restrict__ out) {
    gemm_body<false>(g_C, g_Wo, out);
}

// ---------------------------------------------------------------------------
// Flash attention (R4 structure), tf32 mma, 2-stage cp.async pipeline.
// Block = 64 q rows (128 threads, warp owns 16 rows). Interior tiles
// (k0+64 <= q0) skip causal comparisons entirely (future mask == 0 exactly).
// Reversed q-tile order: longest causal rows first for tail packing.
// Dyn smem: K[2][4096] | V[2][4096] | am[2][64]  (66048 B)
// ---------------------------------------------------------------------------
__global__ void __launch_bounds__(128, 3)
attn_kernel(const float* __restrict__ am) {
    extern __shared__ float sm[];

    const int tid = threadIdx.x;
    const int lane = tid & 31;
    const int w = tid >> 5;
    const int q0 = ((int)gridDim.x - 1 - (int)blockIdx.x) * 64;  // reversed
    const int h = blockIdx.y;
    const int b = blockIdx.z;
    const int bL = b * LL;
    const int r0 = lane >> 2;
    const int j = lane & 3;

    auto issue = [&](int ti) {
        const int k0 = ti * 64;
        const int s = ti & 1;
        float* Ks = sm + s * 4096;
        float* Vs = sm + 8192 + s * 4096;
        float* ams = sm + 16384 + s * 64;
#pragma unroll
        for (int t = 0; t < 8; t++) {
            int id = tid + t * 128;
            int r = id >> 4, c = id & 15;
            const float* gk = &g_K[(bL + k0 + r) * HH + h * HD + (c << 2)];
            const float* gv = &g_V[(bL + k0 + r) * HH + h * HD + (c << 2)];
            cp16(&Ks[r * 64 + ((c ^ (r & 7)) << 2)], gk);
            cp16(&Vs[r * 64 + ((c ^ ((r & 3) << 1)) << 2)], gv);
        }
        if (tid < 16) cp16(&ams[tid << 2], &am[bL + k0 + (tid << 2)]);
        cp_commit();
    };

    // Q fragments (pre-rounded in gmem -> raw bits are valid tf32)
    unsigned qa[8][4];
    const float* Qp = g_Q + (bL + q0 + w * 16) * HH + h * HD;
#pragma unroll
    for (int ks = 0; ks < 8; ks++) {
        qa[ks][0] = __float_as_uint(Qp[r0 * HH + ks * 8 + j]);
        qa[ks][1] = __float_as_uint(Qp[(r0 + 8) * HH + ks * 8 + j]);
        qa[ks][2] = __float_as_uint(Qp[r0 * HH + ks * 8 + j + 4]);
        qa[ks][3] = __float_as_uint(Qp[(r0 + 8) * HH + ks * 8 + j + 4]);
    }
    const float amq0 = am[bL + q0 + w * 16 + r0];
    const float amq1 = am[bL + q0 + w * 16 + r0 + 8];
    const int qi0 = q0 + w * 16 + r0;
    const int qi1 = qi0 + 8;

    float o[8][4] = {};
    float mr0 = -CUDART_INF_F, mr1 = -CUDART_INF_F;
    float l0 = 0.0f, l1 = 0.0f;

    const int ntiles = q0 / 64 + 1;
    issue(0);

    for (int ti = 0; ti < ntiles; ti++) {
        const int k0 = ti * 64;
        cp_wait0();
        __syncthreads();
        if (ti + 1 < ntiles) issue(ti + 1);

        const float* Ks = sm + (ti & 1) * 4096;
        const float* Vs = sm + 8192 + (ti & 1) * 4096;
        const float* ams = sm + 16384 + (ti & 1) * 64;
        const bool interior = (k0 + 64 <= q0);   // future mask identically 0

        // S = Q K^T
        float s[8][4] = {};
#pragma unroll
        for (int ks = 0; ks < 8; ks++) {
            const int pK0 = (((ks << 1) ^ r0) << 2) + j;
            const int pK1 = ((((ks << 1) | 1) ^ r0) << 2) + j;
#pragma unroll
            for (int nt = 0; nt < 8; nt++) {
                unsigned bf[2];
                bf[0] = __float_as_uint(Ks[(nt * 8 + r0) * 64 + pK0]);
                bf[1] = __float_as_uint(Ks[(nt * 8 + r0) * 64 + pK1]);
                mma_tf32(s[nt], qa[ks], bf);
            }
        }

        // Mask (faithful: +FMIN*mask, then /32) + online softmax
        float nm0 = mr0, nm1 = mr1;
        if (interior) {
#pragma unroll
            for (int nt = 0; nt < 8; nt++) {
                float2 ak = *(const float2*)&ams[nt * 8 + (j << 1)];
                float mk0 = 1.f - amq0 * ak.x;
                float mk1 = 1.f - amq0 * ak.y;
                float mk2 = 1.f - amq1 * ak.x;
                float mk3 = 1.f - amq1 * ak.y;
                s[nt][0] = (s[nt][0] + FMIN * mk0) * SOFTMAX_SCALE;
                s[nt][1] = (s[nt][1] + FMIN * mk1) * SOFTMAX_SCALE;
                s[nt][2] = (s[nt][2] + FMIN * mk2) * SOFTMAX_SCALE;
                s[nt][3] = (s[nt][3] + FMIN * mk3) * SOFTMAX_SCALE;
                nm0 = fmaxf(nm0, fmaxf(s[nt][0], s[nt][1]));
                nm1 = fmaxf(nm1, fmaxf(s[nt][2], s[nt][3]));
            }
        } else {
#pragma unroll
            for (int nt = 0; nt < 8; nt++) {
                int kc = k0 + nt * 8 + (j << 1);
                float2 ak = *(const float2*)&ams[nt * 8 + (j << 1)];
                float mk00 = fmaxf((kc > qi0) ? 1.f : 0.f, 1.f - amq0 * ak.x);
                float mk01 = fmaxf((kc + 1 > qi0) ? 1.f : 0.f, 1.f - amq0 * ak.y);
                float mk10 = fmaxf((kc > qi1) ? 1.f : 0.f, 1.f - amq1 * ak.x);
                float mk11 = fmaxf((kc + 1 > qi1) ? 1.f : 0.f, 1.f - amq1 * ak.y);
                s[nt][0] = (s[nt][0] + FMIN * mk00) * SOFTMAX_SCALE;
                s[nt][1] = (s[nt][1] + FMIN * mk01) * SOFTMAX_SCALE;
                s[nt][2] = (s[nt][2] + FMIN * mk10) * SOFTMAX_SCALE;
                s[nt][3] = (s[nt][3] + FMIN * mk11) * SOFTMAX_SCALE;
                nm0 = fmaxf(nm0, fmaxf(s[nt][0], s[nt][1]));
                nm1 = fmaxf(nm1, fmaxf(s[nt][2], s[nt][3]));
            }
        }
        nm0 = fmaxf(nm0, __shfl_xor_sync(0xffffffffu, nm0, 1));
        nm0 = fmaxf(nm0, __shfl_xor_sync(0xffffffffu, nm0, 2));
        nm1 = fmaxf(nm1, __shfl_xor_sync(0xffffffffu, nm1, 1));
        nm1 = fmaxf(nm1, __shfl_xor_sync(0xffffffffu, nm1, 2));

        float corr0 = __expf(mr0 - nm0);
        float corr1 = __expf(mr1 - nm1);
        mr0 = nm0; mr1 = nm1;

        float rs0 = 0.0f, rs1 = 0.0f;
#pragma unroll
        for (int nt = 0; nt < 8; nt++) {
            s[nt][0] = __expf(s[nt][0] - nm0);
            s[nt][1] = __expf(s[nt][1] - nm0);
            s[nt][2] = __expf(s[nt][2] - nm1);
            s[nt][3] = __expf(s[nt][3] - nm1);
            rs0 += s[nt][0] + s[nt][1];
            rs1 += s[nt][2] + s[nt][3];
        }
        rs0 += __shfl_xor_sync(0xffffffffu, rs0, 1);
        rs0 += __shfl_xor_sync(0xffffffffu, rs0, 2);
        rs1 += __shfl_xor_sync(0xffffffffu, rs1, 1);
        rs1 += __shfl_xor_sync(0xffffffffu, rs1, 2);
        l0 = l0 * corr0 + rs0;
        l1 = l1 * corr1 + rs1;
#pragma unroll
        for (int dt = 0; dt < 8; dt++) {
            o[dt][0] *= corr0; o[dt][1] *= corr0;
            o[dt][2] *= corr1; o[dt][3] *= corr1;
        }

        // O += P @ V : permute P (C-layout -> A-layout) via shfl
#pragma unroll
        for (int nt = 0; nt < 8; nt++) {
            unsigned pc0 = f2tf(s[nt][0]), pc1 = f2tf(s[nt][1]);
            unsigned pc2 = f2tf(s[nt][2]), pc3 = f2tf(s[nt][3]);
            int src = (lane & ~3) | (j >> 1);
            int src2 = src + 2;
            unsigned x0 = __shfl_sync(0xffffffffu, pc0, src);
            unsigned x1 = __shfl_sync(0xffffffffu, pc1, src);
            unsigned y0 = __shfl_sync(0xffffffffu, pc2, src);
            unsigned y1 = __shfl_sync(0xffffffffu, pc3, src);
            unsigned x0b = __shfl_sync(0xffffffffu, pc0, src2);
            unsigned x1b = __shfl_sync(0xffffffffu, pc1, src2);
            unsigned y0b = __shfl_sync(0xffffffffu, pc2, src2);
            unsigned y1b = __shfl_sync(0xffffffffu, pc3, src2);
            unsigned af[4];
            af[0] = (lane & 1) ? x1 : x0;
            af[1] = (lane & 1) ? y1 : y0;
            af[2] = (lane & 1) ? x1b : x0b;
            af[3] = (lane & 1) ? y1b : y0b;
#pragma unroll
            for (int dt = 0; dt < 8; dt++) {
                const int pv = ((((dt << 1) | (r0 >> 2)) ^ (j << 1)) << 2) | (r0 & 3);
                unsigned bf[2];
                bf[0] = __float_as_uint(Vs[(nt * 8 + j) * 64 + pv]);
                bf[1] = __float_as_uint(Vs[(nt * 8 + 4 + j) * 64 + pv]);
                mma_tf32(o[dt], af, bf);
            }
        }
    }

    // Normalize, round (next GEMM consumes as tf32), write ctx
    float inv0 = 1.0f / l0, inv1 = 1.0f / l1;
    float* Cp = g_C + (bL + q0 + w * 16) * HH + h * HD;
#pragma unroll
    for (int dt = 0; dt < 8; dt++) {
        int c = dt * 8 + (j << 1);
        *(float2*)&Cp[r0 * HH + c] =
            make_float2(frnd(o[dt][0] * inv0), frnd(o[dt][1] * inv0));
        *(float2*)&Cp[(r0 + 8) * HH + c] =
            make_float2(frnd(o[dt][2] * inv1), frnd(o[dt][3] * inv1));
    }
}

// ---------------------------------------------------------------------------
extern "C" void kernel_launch(void* const* d_in, const int* in_sizes, int n_in,
                              void* d_out, int out_size) {
    const float* input = (const float*)d_in[0];
    const float* amask = (const float*)d_in[1];
    const float* wq = (const float*)d_in[2];
    const float* wk = (const float*)d_in[3];
    const float* wv = (const float*)d_in[4];
    const float* wo = (const float*)d_in[5];
    float* out = (float*)d_out;

    static bool attr_done = false;
    if (!attr_done) {
        cudaFuncSetAttribute(gemm_qkv, cudaFuncAttributeMaxDynamicSharedMemorySize, 98304);
        cudaFuncSetAttribute(gemm_out, cudaFuncAttributeMaxDynamicSharedMemorySize, 98304);
        cudaFuncSetAttribute(attn_kernel, cudaFuncAttributeMaxDynamicSharedMemorySize, 66048);
        attr_done = true;
    }

    preconv_kernel<<<2048, 256>>>(input, wq, wk, wv, wo);
    gemm_qkv<<<dim3(8, 32, 3), 256, 98304>>>();
    attn_kernel<<<dim3(LL / 64, NHEAD, BB), 128, 66048>>>(amask);
    gemm_out<<<dim3(8, 32), 256, 98304>>>(out);
}